// round 2
// baseline (speedup 1.0000x reference)
#include <cuda_runtime.h>
#include <math.h>

#define N_NODES 100000
#define F_IN    256
#define H1      128
#define H2      16
#define C_OUT   40
#define E_EDGES 3200000
#define E_TOT   (E_EDGES + N_NODES)
#define NBLK_N  ((N_NODES + 255) / 256)   // 391

// ---------------- scratch (static device arrays; no runtime alloc) ---------
__device__ __align__(16) float g_h1[N_NODES * H1];      // x @ W1
__device__ __align__(16) float g_a1[N_NODES * H1];      // aggregated + bias + leaky
__device__ __align__(16) float g_h2[N_NODES * H2];
__device__ __align__(16) float g_a2[N_NODES * H2];
__device__ __align__(16) float g_h3[N_NODES * C_OUT];
__device__ int   g_deg[N_NODES];
__device__ float g_dis[N_NODES];          // deg^{-1/2}
__device__ int   g_rowptr[N_NODES + 1];
__device__ int   g_cursor[N_NODES];
__device__ int   g_col[E_TOT];            // src per CSR slot
__device__ float g_wgt[E_TOT];            // dis[src]*dis[dst]
__device__ int   g_bsums[512];
__device__ int   g_boff[512];

#define LEAKY(v) ((v) > 0.f ? (v) : 0.2f * (v))

// ---------------- CSR construction ----------------------------------------
__global__ void k_init_deg() {
    int i = blockIdx.x * blockDim.x + threadIdx.x;
    if (i < N_NODES) g_deg[i] = 1;   // self loop
}

__global__ void k_hist(const int* __restrict__ ei) {
    int e = blockIdx.x * blockDim.x + threadIdx.x;
    if (e < E_EDGES) atomicAdd(&g_deg[ei[E_EDGES + e]], 1);
}

__global__ void k_dis() {
    int i = blockIdx.x * blockDim.x + threadIdx.x;
    if (i < N_NODES) g_dis[i] = rsqrtf((float)g_deg[i]);
}

__global__ void k_scan_block() {
    __shared__ int s[256];
    int b = blockIdx.x, t = threadIdx.x;
    int i = b * 256 + t;
    int v = (i < N_NODES) ? g_deg[i] : 0;
    s[t] = v;
    __syncthreads();
#pragma unroll
    for (int off = 1; off < 256; off <<= 1) {
        int add = (t >= off) ? s[t - off] : 0;
        __syncthreads();
        s[t] += add;
        __syncthreads();
    }
    int incl = s[t];
    if (i < N_NODES) g_rowptr[i] = incl - v;   // exclusive within block
    if (t == 255) g_bsums[b] = incl;
}

__global__ void k_scan_sums(int nblk) {
    __shared__ int s[512];
    int t = threadIdx.x;
    int v = (t < nblk) ? g_bsums[t] : 0;
    s[t] = v;
    __syncthreads();
#pragma unroll
    for (int off = 1; off < 512; off <<= 1) {
        int add = (t >= off) ? s[t - off] : 0;
        __syncthreads();
        s[t] += add;
        __syncthreads();
    }
    int incl = s[t];
    if (t < nblk) g_boff[t] = incl - v;        // exclusive block offset
    if (t == 511) g_rowptr[N_NODES] = incl;    // total == E_TOT
}

__global__ void k_scan_fixup() {
    int i = blockIdx.x * blockDim.x + threadIdx.x;
    if (i < N_NODES) {
        int v = g_rowptr[i] + g_boff[i >> 8];
        g_rowptr[i] = v;
        g_cursor[i] = v;
    }
}

__global__ void k_fill_self() {
    int i = blockIdx.x * blockDim.x + threadIdx.x;
    if (i < N_NODES) {
        int p = atomicAdd(&g_cursor[i], 1);
        float d = g_dis[i];
        g_col[p] = i;
        g_wgt[p] = d * d;
    }
}

__global__ void k_fill_edge(const int* __restrict__ ei) {
    int e = blockIdx.x * blockDim.x + threadIdx.x;
    if (e < E_EDGES) {
        int s = ei[e];
        int d = ei[E_EDGES + e];
        int p = atomicAdd(&g_cursor[d], 1);
        g_col[p] = s;
        g_wgt[p] = g_dis[s] * g_dis[d];
    }
}

// ---------------- GEMM1: h1 = x @ W1  (M=100000, K=256, N=128) -------------
// 128x128 block tile, BK=16, 256 threads, 8x8 register tile.
__global__ __launch_bounds__(256) void k_gemm1(const float* __restrict__ X,
                                               const float* __restrict__ W) {
    __shared__ float As[16][132];   // [k][m], padded
    __shared__ float Bs[16][128];   // [k][n]
    const int block_row = blockIdx.x * 128;
    const int tid = threadIdx.x;

    const int tr = (tid >> 4) * 8;   // 0..120
    const int tc = (tid & 15) * 8;   // 0..120

    float acc[8][8];
#pragma unroll
    for (int i = 0; i < 8; i++)
#pragma unroll
        for (int j = 0; j < 8; j++) acc[i][j] = 0.f;

    for (int k0 = 0; k0 < F_IN; k0 += 16) {
        // load A tile: 128 rows x 16 k, 512 float4, 2 per thread
#pragma unroll
        for (int t = 0; t < 2; t++) {
            int f = tid + t * 256;        // 0..511
            int row = f >> 2;             // 0..127
            int cg  = (f & 3) * 4;        // 0,4,8,12
            int gr = block_row + row;
            float4 v = make_float4(0.f, 0.f, 0.f, 0.f);
            if (gr < N_NODES) v = *(const float4*)&X[(size_t)gr * F_IN + k0 + cg];
            As[cg + 0][row] = v.x;
            As[cg + 1][row] = v.y;
            As[cg + 2][row] = v.z;
            As[cg + 3][row] = v.w;
        }
        // load B tile: 16 k x 128 n, 512 float4, 2 per thread
#pragma unroll
        for (int t = 0; t < 2; t++) {
            int f = tid + t * 256;
            int kr = f >> 5;              // 0..15
            int nc = (f & 31) * 4;        // 0..124
            *(float4*)&Bs[kr][nc] = *(const float4*)&W[(size_t)(k0 + kr) * H1 + nc];
        }
        __syncthreads();

#pragma unroll
        for (int k = 0; k < 16; k++) {
            float4 a0 = *(const float4*)&As[k][tr];
            float4 a1 = *(const float4*)&As[k][tr + 4];
            float4 b0 = *(const float4*)&Bs[k][tc];
            float4 b1 = *(const float4*)&Bs[k][tc + 4];
            float ar[8] = {a0.x, a0.y, a0.z, a0.w, a1.x, a1.y, a1.z, a1.w};
            float br[8] = {b0.x, b0.y, b0.z, b0.w, b1.x, b1.y, b1.z, b1.w};
#pragma unroll
            for (int i = 0; i < 8; i++)
#pragma unroll
                for (int j = 0; j < 8; j++) acc[i][j] += ar[i] * br[j];
        }
        __syncthreads();
    }

#pragma unroll
    for (int i = 0; i < 8; i++) {
        int gr = block_row + tr + i;
        if (gr < N_NODES) {
            float4 v0 = make_float4(acc[i][0], acc[i][1], acc[i][2], acc[i][3]);
            float4 v1 = make_float4(acc[i][4], acc[i][5], acc[i][6], acc[i][7]);
            *(float4*)&g_h1[(size_t)gr * H1 + tc]     = v0;
            *(float4*)&g_h1[(size_t)gr * H1 + tc + 4] = v1;
        }
    }
}

// ---------------- Aggregation layer 1 (dim 128): warp per node -------------
__global__ __launch_bounds__(256) void k_agg1(const float* __restrict__ b1) {
    int n = blockIdx.x * 8 + (threadIdx.x >> 5);
    int lane = threadIdx.x & 31;
    if (n >= N_NODES) return;
    int s0 = g_rowptr[n], s1 = g_rowptr[n + 1];
    float4 bv = *(const float4*)&b1[lane * 4];
    float4 acc = bv;
    const float4* h = (const float4*)g_h1;
    for (int e = s0; e < s1; e++) {
        int src = g_col[e];
        float w = g_wgt[e];
        float4 v = h[(size_t)src * 32 + lane];
        acc.x += w * v.x; acc.y += w * v.y; acc.z += w * v.z; acc.w += w * v.w;
    }
    acc.x = LEAKY(acc.x); acc.y = LEAKY(acc.y);
    acc.z = LEAKY(acc.z); acc.w = LEAKY(acc.w);
    ((float4*)g_a1)[(size_t)n * 32 + lane] = acc;
}

// ---------------- GEMM2: h2 = a1 @ W2  (K=128, N=16) -----------------------
__global__ __launch_bounds__(256) void k_gemm2(const float* __restrict__ W) {
    __shared__ float Xs[16][128];
    __shared__ float Ws[128 * 16];
    const int rbase = blockIdx.x * 16;
    const int tid = threadIdx.x;
    // load 16 rows x 128 cols of a1
#pragma unroll
    for (int t = 0; t < 2; t++) {
        int f = tid + t * 256;      // float4 index, 512 total
        int row = f >> 5;           // 0..15
        int col = (f & 31) * 4;
        *(float4*)&Xs[row][col] = *(const float4*)&g_a1[(size_t)(rbase + row) * H1 + col];
    }
    for (int i = tid; i < 128 * 16; i += 256) Ws[i] = W[i];
    __syncthreads();

    int r = tid >> 4;       // 0..15
    int c = tid & 15;       // 0..15
    float acc = 0.f;
#pragma unroll 8
    for (int k = 0; k < 128; k++) acc += Xs[r][k] * Ws[k * 16 + c];
    g_h2[(size_t)(rbase + r) * H2 + c] = acc;
}

// ---------------- Aggregation layer 2 (dim 16): 16 threads per node --------
__global__ __launch_bounds__(256) void k_agg2(const float* __restrict__ b2) {
    int n = blockIdx.x * 16 + (threadIdx.x >> 4);
    int f = threadIdx.x & 15;
    if (n >= N_NODES) return;
    int s0 = g_rowptr[n], s1 = g_rowptr[n + 1];
    float acc = b2[f];
    for (int e = s0; e < s1; e++) {
        int src = g_col[e];
        float w = g_wgt[e];
        acc += w * g_h2[(size_t)src * H2 + f];
    }
    acc = LEAKY(acc);
    g_a2[(size_t)n * H2 + f] = acc;
}

// ---------------- GEMM3: h3 = a2 @ W3  (K=16, N=40) ------------------------
__global__ __launch_bounds__(256) void k_gemm3(const float* __restrict__ W) {
    __shared__ float Ws[16 * 40];
    __shared__ float Xs[64][17];     // 64 rows x 16, padded
    const int rbase = blockIdx.x * 64;
    const int tid = threadIdx.x;
    for (int i = tid; i < 16 * 40; i += 256) Ws[i] = W[i];
    // load 64 rows x 16 of a2 (1024 floats, 4 per thread, coalesced)
#pragma unroll
    for (int t = 0; t < 4; t++) {
        int f = tid + t * 256;      // 0..1023
        int row = f >> 4;
        int col = f & 15;
        Xs[row][col] = (rbase + row < N_NODES)
                       ? g_a2[(size_t)(rbase + row) * H2 + col] : 0.f;
    }
    __syncthreads();
    // 64*40 = 2560 outputs, 10 per thread
#pragma unroll
    for (int t = 0; t < 10; t++) {
        int o = tid + t * 256;
        int r = o / C_OUT;
        int c = o % C_OUT;
        float acc = 0.f;
#pragma unroll
        for (int k = 0; k < 16; k++) acc += Xs[r][k] * Ws[k * C_OUT + c];
        if (rbase + r < N_NODES)
            g_h3[(size_t)(rbase + r) * C_OUT + c] = acc;
    }
}

// ---------------- Aggregation layer 3 (dim 40): warp per node --------------
__global__ __launch_bounds__(256) void k_agg3(const float* __restrict__ b3,
                                              float* __restrict__ out) {
    int n = blockIdx.x * 8 + (threadIdx.x >> 5);
    int lane = threadIdx.x & 31;
    if (n >= N_NODES) return;
    int s0 = g_rowptr[n], s1 = g_rowptr[n + 1];
    float acc0 = b3[lane];
    float acc1 = (lane < 8) ? b3[32 + lane] : 0.f;
    for (int e = s0; e < s1; e++) {
        int src = g_col[e];
        float w = g_wgt[e];
        const float* row = &g_h3[(size_t)src * C_OUT];
        acc0 += w * row[lane];
        if (lane < 8) acc1 += w * row[32 + lane];
    }
    out[(size_t)n * C_OUT + lane] = acc0;
    if (lane < 8) out[(size_t)n * C_OUT + 32 + lane] = acc1;
}

// ---------------- launch ----------------------------------------------------
extern "C" void kernel_launch(void* const* d_in, const int* in_sizes, int n_in,
                              void* d_out, int out_size) {
    const float* x  = (const float*)d_in[0];
    const int*   ei = (const int*)d_in[1];     // int32! (JAX x64 disabled)
    const float* W1 = (const float*)d_in[2];
    const float* b1 = (const float*)d_in[3];
    const float* W2 = (const float*)d_in[4];
    const float* b2 = (const float*)d_in[5];
    const float* W3 = (const float*)d_in[6];
    const float* b3 = (const float*)d_in[7];
    float* out = (float*)d_out;

    const int TB = 256;
    const int gN = NBLK_N;                       // 391
    const int gE = (E_EDGES + TB - 1) / TB;      // 12500

    // CSR build
    k_init_deg<<<gN, TB>>>();
    k_hist<<<gE, TB>>>(ei);
    k_dis<<<gN, TB>>>();
    k_scan_block<<<gN, TB>>>();
    k_scan_sums<<<1, 512>>>(gN);
    k_scan_fixup<<<gN, TB>>>();
    k_fill_self<<<gN, TB>>>();
    k_fill_edge<<<gE, TB>>>(ei);

    // layer 1
    k_gemm1<<<(N_NODES + 127) / 128, 256>>>(x, W1);
    k_agg1<<<N_NODES / 8, 256>>>(b1);
    // layer 2
    k_gemm2<<<N_NODES / 16, 256>>>(W2);
    k_agg2<<<N_NODES / 16, 256>>>(b2);
    // layer 3
    k_gemm3<<<(N_NODES + 63) / 64, 256>>>(W3);
    k_agg3<<<N_NODES / 8, 256>>>(b3, out);
}

// round 4
// speedup vs baseline: 1.1657x; 1.1657x over previous
#include <cuda_runtime.h>
#include <cuda_bf16.h>
#include <math.h>
#include <stdint.h>

#define N_NODES 100000
#define F_IN    256
#define H1      128
#define H2      16
#define C_OUT   40
#define E_EDGES 3200000
#define E_TOT   (E_EDGES + N_NODES)
#define NBLK_N  ((N_NODES + 255) / 256)   // 391

// ---------------- scratch (static device arrays; no runtime alloc) ---------
__device__ __align__(16) float g_h1[N_NODES * H1];      // x @ W1
__device__ __align__(16) float g_a1[N_NODES * H1];      // leaky(agg(h1)+b1)
__device__ __align__(16) float g_h2[N_NODES * H2];
__device__ __align__(16) float g_a2[N_NODES * H2];
__device__ __align__(16) float g_g3[N_NODES * H2];      // agg(a2)
__device__ __align__(16) __nv_bfloat16 g_wt_hi[H1 * F_IN];  // W1^T hi split [n][k]
__device__ __align__(16) __nv_bfloat16 g_wt_lo[H1 * F_IN];  // W1^T lo split [n][k]
__device__ int   g_deg[N_NODES];
__device__ float g_dis[N_NODES];          // deg^{-1/2}
__device__ int   g_rowptr[N_NODES + 1];
__device__ int   g_cursor[N_NODES];
__device__ int   g_col[E_TOT];            // src per CSR slot
__device__ float g_wgt[E_TOT];            // dis[src]*dis[dst]
__device__ int   g_bsums[512];
__device__ int   g_boff[512];

#define LEAKY(v) ((v) > 0.f ? (v) : 0.2f * (v))

// ===================== portable tensor-core helpers (sm_80+) ================
__device__ __forceinline__ uint32_t smem_u32(const void* p) {
    uint32_t a;
    asm("{ .reg .u64 t; cvta.to.shared.u64 t, %1; cvt.u32.u64 %0, t; }"
        : "=r"(a) : "l"(p));
    return a;
}
__device__ __forceinline__ void ldmx4(uint32_t& r0, uint32_t& r1,
                                      uint32_t& r2, uint32_t& r3, uint32_t a) {
    asm volatile("ldmatrix.sync.aligned.m8n8.x4.shared.b16 {%0,%1,%2,%3}, [%4];"
                 : "=r"(r0), "=r"(r1), "=r"(r2), "=r"(r3) : "r"(a));
}
__device__ __forceinline__ void mma_bf16(float* d, const uint32_t* a,
                                         uint32_t b0, uint32_t b1) {
    asm volatile(
        "mma.sync.aligned.m16n8k16.row.col.f32.bf16.bf16.f32 "
        "{%0,%1,%2,%3}, {%4,%5,%6,%7}, {%8,%9}, {%0,%1,%2,%3};"
        : "+f"(d[0]), "+f"(d[1]), "+f"(d[2]), "+f"(d[3])
        : "r"(a[0]), "r"(a[1]), "r"(a[2]), "r"(a[3]), "r"(b0), "r"(b1));
}

// ---------------- CSR construction ----------------------------------------
__global__ void k_init_deg() {
    int i = blockIdx.x * blockDim.x + threadIdx.x;
    if (i < N_NODES) g_deg[i] = 1;   // self loop
}
__global__ void k_hist(const int* __restrict__ ei) {
    int e = blockIdx.x * blockDim.x + threadIdx.x;
    if (e < E_EDGES) atomicAdd(&g_deg[ei[E_EDGES + e]], 1);
}
__global__ void k_scan_block() {
    __shared__ int s[256];
    int b = blockIdx.x, t = threadIdx.x;
    int i = b * 256 + t;
    int v = (i < N_NODES) ? g_deg[i] : 0;
    if (i < N_NODES) g_dis[i] = rsqrtf((float)v);
    s[t] = v;
    __syncthreads();
#pragma unroll
    for (int off = 1; off < 256; off <<= 1) {
        int add = (t >= off) ? s[t - off] : 0;
        __syncthreads();
        s[t] += add;
        __syncthreads();
    }
    int incl = s[t];
    if (i < N_NODES) g_rowptr[i] = incl - v;
    if (t == 255) g_bsums[b] = incl;
}
__global__ void k_scan_sums(int nblk) {
    __shared__ int s[512];
    int t = threadIdx.x;
    int v = (t < nblk) ? g_bsums[t] : 0;
    s[t] = v;
    __syncthreads();
#pragma unroll
    for (int off = 1; off < 512; off <<= 1) {
        int add = (t >= off) ? s[t - off] : 0;
        __syncthreads();
        s[t] += add;
        __syncthreads();
    }
    int incl = s[t];
    if (t < nblk) g_boff[t] = incl - v;
    if (t == 511) g_rowptr[N_NODES] = incl;
}
__global__ void k_scan_fixup() {   // + self-loop fill + cursor init
    int i = blockIdx.x * blockDim.x + threadIdx.x;
    if (i < N_NODES) {
        int v = g_rowptr[i] + g_boff[i >> 8];
        g_rowptr[i] = v;
        g_cursor[i] = v + 1;
        g_col[v] = i;
        float d = g_dis[i];
        g_wgt[v] = d * d;
    }
}
__global__ void k_fill_edge(const int* __restrict__ ei) {
    int e = blockIdx.x * blockDim.x + threadIdx.x;
    if (e < E_EDGES) {
        int s = ei[e];
        int d = ei[E_EDGES + e];
        int p = atomicAdd(&g_cursor[d], 1);
        g_col[p] = s;
        g_wgt[p] = g_dis[s] * g_dis[d];
    }
}

// ---------------- W1 transpose + bf16 split --------------------------------
__global__ void k_prepw(const float* __restrict__ W1) {
    int idx = blockIdx.x * blockDim.x + threadIdx.x;  // 32768
    if (idx < F_IN * H1) {
        int k = idx >> 7, n = idx & 127;
        float w = W1[idx];
        __nv_bfloat16 hi = __float2bfloat16_rn(w);
        float lo = w - __bfloat162float(hi);
        g_wt_hi[n * F_IN + k] = hi;
        g_wt_lo[n * F_IN + k] = __float2bfloat16_rn(lo);
    }
}

// ---------------- GEMM1: h1 = X @ W1, bf16 split via mma.sync --------------
// CTA 128x128, BK=32, 8 warps in 2(m) x 4(n): warp tile 64x32.
// SMEM rows padded to 40 bf16 (80 B) -> conflict-free ldmatrix.
#define PADK 40
__global__ __launch_bounds__(256) void k_gemm1(const float* __restrict__ X) {
    __shared__ __align__(16) __nv_bfloat16 sAhi[128 * PADK];
    __shared__ __align__(16) __nv_bfloat16 sAlo[128 * PADK];
    __shared__ __align__(16) __nv_bfloat16 sBhi[128 * PADK];
    __shared__ __align__(16) __nv_bfloat16 sBlo[128 * PADK];

    const int tid = threadIdx.x, wid = tid >> 5, lane = tid & 31;
    const int wm = wid & 1, wn = wid >> 1;          // warp grid 2x4
    const int blockRow = blockIdx.x * 128;

    const uint32_t aHi = smem_u32(sAhi), aLo = smem_u32(sAlo);
    const uint32_t bHi = smem_u32(sBhi), bLo = smem_u32(sBlo);

    // staging roles: thread -> (row, k-half)
    const int srow = tid >> 1;          // 0..127
    const int skh  = (tid & 1) * 16;    // 0 or 16 (k offset in chunk)
    const int grow = blockRow + srow;
    const uint32_t soff = (uint32_t)(srow * PADK + skh) * 2;   // byte offset

    // ldmatrix per-lane offsets (byte)
    // A: row = wm*64 + mt*16 + (lane&15), k = (lane>>4)*8
    const uint32_t aLaneOff =
        (uint32_t)((wm * 64 + (lane & 15)) * PADK + (lane >> 4) * 8) * 2;
    // B: n = wn*32 + p*16 + (lane&7) + (lane>>4)*8, k = ((lane>>3)&1)*8
    const uint32_t bLaneOff =
        (uint32_t)((wn * 32 + (lane & 7) + (lane >> 4) * 8) * PADK +
                   ((lane >> 3) & 1) * 8) * 2;

    float acc[4][4][4];
#pragma unroll
    for (int i = 0; i < 4; i++)
#pragma unroll
        for (int j = 0; j < 4; j++)
#pragma unroll
            for (int q = 0; q < 4; q++) acc[i][j][q] = 0.f;

    for (int c = 0; c < 8; c++) {          // K chunks of 32
        // ---- stage A: 128 rows x 32 k fp32 -> bf16 hi/lo ----
        {
            const float* xp = X + (size_t)grow * F_IN + c * 32 + skh;
            float f[16];
#pragma unroll
            for (int j = 0; j < 4; j++) {
                float4 v = (grow < N_NODES) ? *(const float4*)(xp + j * 4)
                                            : make_float4(0.f, 0.f, 0.f, 0.f);
                f[4*j] = v.x; f[4*j+1] = v.y; f[4*j+2] = v.z; f[4*j+3] = v.w;
            }
            uint32_t ph[8], pl[8];
#pragma unroll
            for (int q = 0; q < 8; q++) {
                __nv_bfloat16 h0 = __float2bfloat16_rn(f[2*q]);
                __nv_bfloat16 h1 = __float2bfloat16_rn(f[2*q+1]);
                __nv_bfloat16 l0 = __float2bfloat16_rn(f[2*q]   - __bfloat162float(h0));
                __nv_bfloat16 l1 = __float2bfloat16_rn(f[2*q+1] - __bfloat162float(h1));
                ph[q] = (uint32_t)*(unsigned short*)&h0 |
                        ((uint32_t)*(unsigned short*)&h1 << 16);
                pl[q] = (uint32_t)*(unsigned short*)&l0 |
                        ((uint32_t)*(unsigned short*)&l1 << 16);
            }
            *(uint4*)((char*)sAhi + soff)      = make_uint4(ph[0], ph[1], ph[2], ph[3]);
            *(uint4*)((char*)sAhi + soff + 16) = make_uint4(ph[4], ph[5], ph[6], ph[7]);
            *(uint4*)((char*)sAlo + soff)      = make_uint4(pl[0], pl[1], pl[2], pl[3]);
            *(uint4*)((char*)sAlo + soff + 16) = make_uint4(pl[4], pl[5], pl[6], pl[7]);
        }
        // ---- stage B: pre-split W1^T [n][k] bf16 ----
        {
            const uint4* wh = (const uint4*)(g_wt_hi + srow * F_IN + c * 32 + skh);
            const uint4* wl = (const uint4*)(g_wt_lo + srow * F_IN + c * 32 + skh);
            *(uint4*)((char*)sBhi + soff)      = wh[0];
            *(uint4*)((char*)sBhi + soff + 16) = wh[1];
            *(uint4*)((char*)sBlo + soff)      = wl[0];
            *(uint4*)((char*)sBlo + soff + 16) = wl[1];
        }
        __syncthreads();

#pragma unroll
        for (int ks = 0; ks < 2; ks++) {    // two k16 steps per chunk
            const uint32_t kb = (uint32_t)(ks * 16 * 2);
            // B fragments: 4 n8-tiles via 2 ldmatrix.x4 each for hi and lo
            uint32_t bh[4][2], bl[4][2];
#pragma unroll
            for (int p = 0; p < 2; p++) {
                uint32_t addr = bLaneOff + (uint32_t)(p * 16 * PADK * 2) + kb;
                uint32_t r0, r1, r2, r3;
                ldmx4(r0, r1, r2, r3, bHi + addr);
                bh[2*p][0] = r0; bh[2*p][1] = r1;
                bh[2*p+1][0] = r2; bh[2*p+1][1] = r3;
                ldmx4(r0, r1, r2, r3, bLo + addr);
                bl[2*p][0] = r0; bl[2*p][1] = r1;
                bl[2*p+1][0] = r2; bl[2*p+1][1] = r3;
            }
#pragma unroll
            for (int mt = 0; mt < 4; mt++) {
                uint32_t addr = aLaneOff + (uint32_t)(mt * 16 * PADK * 2) + kb;
                uint32_t ah[4], al[4];
                ldmx4(ah[0], ah[1], ah[2], ah[3], aHi + addr);
                ldmx4(al[0], al[1], al[2], al[3], aLo + addr);
#pragma unroll
                for (int nt = 0; nt < 4; nt++) {
                    mma_bf16(acc[mt][nt], ah, bh[nt][0], bh[nt][1]); // hi*hi
                    mma_bf16(acc[mt][nt], ah, bl[nt][0], bl[nt][1]); // hi*lo
                    mma_bf16(acc[mt][nt], al, bh[nt][0], bh[nt][1]); // lo*hi
                }
            }
        }
        __syncthreads();
    }

    // ---- epilogue ----
    const int r0 = blockRow + wm * 64 + (lane >> 2);
    const int c0 = wn * 32 + 2 * (lane & 3);
#pragma unroll
    for (int mt = 0; mt < 4; mt++) {
#pragma unroll
        for (int nt = 0; nt < 4; nt++) {
            int rA = r0 + mt * 16;
            int cc = c0 + nt * 8;
            if (rA < N_NODES)
                *(float2*)&g_h1[(size_t)rA * H1 + cc] =
                    make_float2(acc[mt][nt][0], acc[mt][nt][1]);
            if (rA + 8 < N_NODES)
                *(float2*)&g_h1[(size_t)(rA + 8) * H1 + cc] =
                    make_float2(acc[mt][nt][2], acc[mt][nt][3]);
        }
    }
}

// ---------------- Aggregation layer 1 (dim 128): warp per node -------------
__global__ __launch_bounds__(256) void k_agg1(const float* __restrict__ b1) {
    int n = blockIdx.x * 8 + (threadIdx.x >> 5);
    int lane = threadIdx.x & 31;
    if (n >= N_NODES) return;
    int s0 = g_rowptr[n], s1 = g_rowptr[n + 1];
    float4 acc = *(const float4*)&b1[lane * 4];
    const float4* h = (const float4*)g_h1;
    int e = s0;
    for (; e + 1 < s1; e += 2) {
        int src0 = g_col[e],     src1 = g_col[e + 1];
        float w0 = g_wgt[e],     w1 = g_wgt[e + 1];
        float4 v0 = h[(size_t)src0 * 32 + lane];
        float4 v1 = h[(size_t)src1 * 32 + lane];
        acc.x += w0 * v0.x + w1 * v1.x;
        acc.y += w0 * v0.y + w1 * v1.y;
        acc.z += w0 * v0.z + w1 * v1.z;
        acc.w += w0 * v0.w + w1 * v1.w;
    }
    if (e < s1) {
        int src = g_col[e]; float w = g_wgt[e];
        float4 v = h[(size_t)src * 32 + lane];
        acc.x += w * v.x; acc.y += w * v.y; acc.z += w * v.z; acc.w += w * v.w;
    }
    acc.x = LEAKY(acc.x); acc.y = LEAKY(acc.y);
    acc.z = LEAKY(acc.z); acc.w = LEAKY(acc.w);
    ((float4*)g_a1)[(size_t)n * 32 + lane] = acc;
}

// ---------------- GEMM2: h2 = a1 @ W2  (K=128, N=16) -----------------------
__global__ __launch_bounds__(256) void k_gemm2(const float* __restrict__ W) {
    __shared__ float Xs[16][128];
    __shared__ float Ws[128 * 16];
    const int rbase = blockIdx.x * 16;
    const int tid = threadIdx.x;
#pragma unroll
    for (int t = 0; t < 2; t++) {
        int f = tid + t * 256;
        int row = f >> 5;
        int col = (f & 31) * 4;
        *(float4*)&Xs[row][col] = *(const float4*)&g_a1[(size_t)(rbase + row) * H1 + col];
    }
    for (int i = tid; i < 128 * 16; i += 256) Ws[i] = W[i];
    __syncthreads();
    int r = tid >> 4, c = tid & 15;
    float acc = 0.f;
#pragma unroll 8
    for (int k = 0; k < 128; k++) acc += Xs[r][k] * Ws[k * 16 + c];
    g_h2[(size_t)(rbase + r) * H2 + c] = acc;
}

// ---------------- Aggregation layer 2 (dim 16) ------------------------------
__global__ __launch_bounds__(256) void k_agg2(const float* __restrict__ b2) {
    int n = blockIdx.x * 16 + (threadIdx.x >> 4);
    int f = threadIdx.x & 15;
    if (n >= N_NODES) return;
    int s0 = g_rowptr[n], s1 = g_rowptr[n + 1];
    float acc = b2[f];
    for (int e = s0; e < s1; e++) {
        acc += g_wgt[e] * g_h2[(size_t)g_col[e] * H2 + f];
    }
    g_a2[(size_t)n * H2 + f] = LEAKY(acc);
}

// ---------------- Aggregation layer 3 (dim 16, before GEMM3) ----------------
__global__ __launch_bounds__(256) void k_agg3g() {
    int n = blockIdx.x * 16 + (threadIdx.x >> 4);
    int f = threadIdx.x & 15;
    if (n >= N_NODES) return;
    int s0 = g_rowptr[n], s1 = g_rowptr[n + 1];
    float acc = 0.f;
    for (int e = s0; e < s1; e++) {
        acc += g_wgt[e] * g_a2[(size_t)g_col[e] * H2 + f];
    }
    g_g3[(size_t)n * H2 + f] = acc;
}

// ---------------- GEMM3: out = g3 @ W3 + b3  (K=16, N=40) ------------------
__global__ __launch_bounds__(256) void k_gemm3(const float* __restrict__ W,
                                               const float* __restrict__ b3,
                                               float* __restrict__ out) {
    __shared__ float Ws[16 * 40];
    __shared__ float Bs[40];
    __shared__ float Xs[64][17];
    const int rbase = blockIdx.x * 64;
    const int tid = threadIdx.x;
    for (int i = tid; i < 16 * 40; i += 256) Ws[i] = W[i];
    if (tid < 40) Bs[tid] = b3[tid];
#pragma unroll
    for (int t = 0; t < 4; t++) {
        int f = tid + t * 256;
        int row = f >> 4;
        int col = f & 15;
        Xs[row][col] = (rbase + row < N_NODES)
                       ? g_g3[(size_t)(rbase + row) * H2 + col] : 0.f;
    }
    __syncthreads();
#pragma unroll
    for (int t = 0; t < 10; t++) {
        int o = tid + t * 256;
        int r = o / C_OUT;
        int c = o % C_OUT;
        float acc = Bs[c];
#pragma unroll
        for (int k = 0; k < 16; k++) acc += Xs[r][k] * Ws[k * C_OUT + c];
        if (rbase + r < N_NODES)
            out[(size_t)(rbase + r) * C_OUT + c] = acc;
    }
}

// ---------------- launch ----------------------------------------------------
extern "C" void kernel_launch(void* const* d_in, const int* in_sizes, int n_in,
                              void* d_out, int out_size) {
    const float* x  = (const float*)d_in[0];
    const int*   ei = (const int*)d_in[1];     // int32 (JAX x64 disabled)
    const float* W1 = (const float*)d_in[2];
    const float* b1 = (const float*)d_in[3];
    const float* W2 = (const float*)d_in[4];
    const float* b2 = (const float*)d_in[5];
    const float* W3 = (const float*)d_in[6];
    const float* b3 = (const float*)d_in[7];
    float* out = (float*)d_out;

    const int TB = 256;
    const int gN = NBLK_N;                       // 391
    const int gE = (E_EDGES + TB - 1) / TB;      // 12500

    // CSR build
    k_init_deg<<<gN, TB>>>();
    k_hist<<<gE, TB>>>(ei);
    k_scan_block<<<gN, TB>>>();
    k_scan_sums<<<1, 512>>>(gN);
    k_scan_fixup<<<gN, TB>>>();
    k_fill_edge<<<gE, TB>>>(ei);

    // layer 1 (tensor GEMM + gather-agg)
    k_prepw<<<(F_IN * H1 + TB - 1) / TB, TB>>>(W1);
    k_gemm1<<<(N_NODES + 127) / 128, 256>>>(x);
    k_agg1<<<N_NODES / 8, 256>>>(b1);
    // layer 2
    k_gemm2<<<N_NODES / 16, 256>>>(W2);
    k_agg2<<<N_NODES / 16, 256>>>(b2);
    // layer 3 (agg first, then GEMM with bias)
    k_agg3g<<<N_NODES / 16, 256>>>();
    k_gemm3<<<(N_NODES + 63) / 64, 256>>>(W3, b3, out);
}

// round 5
// speedup vs baseline: 1.3322x; 1.1429x over previous
#include <cuda_runtime.h>
#include <cuda_bf16.h>
#include <cuda_fp16.h>
#include <math.h>
#include <stdint.h>

#define N_NODES 100000
#define F_IN    256
#define H1      128
#define H2      16
#define C_OUT   40
#define E_EDGES 3200000
#define E_TOT   (E_EDGES + N_NODES)
#define NBLK_N  ((N_NODES + 255) / 256)   // 391

// ---------------- scratch (static device arrays; no runtime alloc) ---------
__device__ __align__(16) __half g_h1[N_NODES * H1];     // x @ W1 (fp16)
__device__ __align__(16) float  g_a1[N_NODES * H1];     // leaky(agg(h1)+b1)
__device__ __align__(16) __half g_h2[N_NODES * H2];     // a1 @ W2 (fp16)
__device__ __align__(16) __half g_a2[N_NODES * H2];     // leaky(agg(h2)+b2) fp16
__device__ __align__(16) float  g_g3[N_NODES * H2];     // agg(a2) fp32
__device__ __align__(16) __nv_bfloat16 g_wt_hi[H1 * F_IN];  // W1^T hi split [n][k]
__device__ __align__(16) __nv_bfloat16 g_wt_lo[H1 * F_IN];  // W1^T lo split [n][k]
__device__ int   g_deg[N_NODES];
__device__ float g_dis[N_NODES];          // deg^{-1/2}
__device__ int   g_rowptr[N_NODES + 1];
__device__ int   g_cursor[N_NODES];
__device__ int   g_col[E_TOT];            // src per CSR slot
__device__ float g_wgt[E_TOT];            // dis[src]*dis[dst]
__device__ int   g_bsums[512];
__device__ int   g_boff[512];

#define LEAKY(v) ((v) > 0.f ? (v) : 0.2f * (v))

// ===================== portable tensor-core helpers (sm_80+) ================
__device__ __forceinline__ uint32_t smem_u32(const void* p) {
    uint32_t a;
    asm("{ .reg .u64 t; cvta.to.shared.u64 t, %1; cvt.u32.u64 %0, t; }"
        : "=r"(a) : "l"(p));
    return a;
}
__device__ __forceinline__ void ldmx4(uint32_t& r0, uint32_t& r1,
                                      uint32_t& r2, uint32_t& r3, uint32_t a) {
    asm volatile("ldmatrix.sync.aligned.m8n8.x4.shared.b16 {%0,%1,%2,%3}, [%4];"
                 : "=r"(r0), "=r"(r1), "=r"(r2), "=r"(r3) : "r"(a));
}
__device__ __forceinline__ void mma_bf16(float* d, const uint32_t* a,
                                         uint32_t b0, uint32_t b1) {
    asm volatile(
        "mma.sync.aligned.m16n8k16.row.col.f32.bf16.bf16.f32 "
        "{%0,%1,%2,%3}, {%4,%5,%6,%7}, {%8,%9}, {%0,%1,%2,%3};"
        : "+f"(d[0]), "+f"(d[1]), "+f"(d[2]), "+f"(d[3])
        : "r"(a[0]), "r"(a[1]), "r"(a[2]), "r"(a[3]), "r"(b0), "r"(b1));
}

// ---------------- CSR construction ----------------------------------------
__global__ void k_init_deg() {
    int i = blockIdx.x * blockDim.x + threadIdx.x;
    if (i < N_NODES) g_deg[i] = 1;   // self loop
}
__global__ void k_hist(const int* __restrict__ ei) {
    int e = blockIdx.x * blockDim.x + threadIdx.x;
    if (e < E_EDGES) atomicAdd(&g_deg[ei[E_EDGES + e]], 1);
}
__global__ void k_scan_block() {
    __shared__ int s[256];
    int b = blockIdx.x, t = threadIdx.x;
    int i = b * 256 + t;
    int v = (i < N_NODES) ? g_deg[i] : 0;
    if (i < N_NODES) g_dis[i] = rsqrtf((float)v);
    s[t] = v;
    __syncthreads();
#pragma unroll
    for (int off = 1; off < 256; off <<= 1) {
        int add = (t >= off) ? s[t - off] : 0;
        __syncthreads();
        s[t] += add;
        __syncthreads();
    }
    int incl = s[t];
    if (i < N_NODES) g_rowptr[i] = incl - v;
    if (t == 255) g_bsums[b] = incl;
}
__global__ void k_scan_sums(int nblk) {
    __shared__ int s[512];
    int t = threadIdx.x;
    int v = (t < nblk) ? g_bsums[t] : 0;
    s[t] = v;
    __syncthreads();
#pragma unroll
    for (int off = 1; off < 512; off <<= 1) {
        int add = (t >= off) ? s[t - off] : 0;
        __syncthreads();
        s[t] += add;
        __syncthreads();
    }
    int incl = s[t];
    if (t < nblk) g_boff[t] = incl - v;
    if (t == 511) g_rowptr[N_NODES] = incl;
}
__global__ void k_scan_fixup() {   // + self-loop fill + cursor init
    int i = blockIdx.x * blockDim.x + threadIdx.x;
    if (i < N_NODES) {
        int v = g_rowptr[i] + g_boff[i >> 8];
        g_rowptr[i] = v;
        g_cursor[i] = v + 1;
        g_col[v] = i;
        float d = g_dis[i];
        g_wgt[v] = d * d;
    }
}
__global__ void k_fill_edge(const int* __restrict__ ei) {
    int e = blockIdx.x * blockDim.x + threadIdx.x;
    if (e < E_EDGES) {
        int s = ei[e];
        int d = ei[E_EDGES + e];
        int p = atomicAdd(&g_cursor[d], 1);
        g_col[p] = s;
        g_wgt[p] = g_dis[s] * g_dis[d];
    }
}

// ---------------- W1 transpose + bf16 split --------------------------------
__global__ void k_prepw(const float* __restrict__ W1) {
    int idx = blockIdx.x * blockDim.x + threadIdx.x;  // 32768
    if (idx < F_IN * H1) {
        int k = idx >> 7, n = idx & 127;
        float w = W1[idx];
        __nv_bfloat16 hi = __float2bfloat16_rn(w);
        float lo = w - __bfloat162float(hi);
        g_wt_hi[n * F_IN + k] = hi;
        g_wt_lo[n * F_IN + k] = __float2bfloat16_rn(lo);
    }
}

// ---------------- GEMM1: h1 = X @ W1, bf16 split via mma.sync --------------
// CTA 128x128, BK=32, 8 warps in 2(m) x 4(n): warp tile 64x32.
#define PADK 40
__global__ __launch_bounds__(256) void k_gemm1(const float* __restrict__ X) {
    __shared__ __align__(16) __nv_bfloat16 sAhi[128 * PADK];
    __shared__ __align__(16) __nv_bfloat16 sAlo[128 * PADK];
    __shared__ __align__(16) __nv_bfloat16 sBhi[128 * PADK];
    __shared__ __align__(16) __nv_bfloat16 sBlo[128 * PADK];

    const int tid = threadIdx.x, wid = tid >> 5, lane = tid & 31;
    const int wm = wid & 1, wn = wid >> 1;          // warp grid 2x4
    const int blockRow = blockIdx.x * 128;

    const uint32_t aHi = smem_u32(sAhi), aLo = smem_u32(sAlo);
    const uint32_t bHi = smem_u32(sBhi), bLo = smem_u32(sBlo);

    const int srow = tid >> 1;          // 0..127
    const int skh  = (tid & 1) * 16;    // 0 or 16
    const int grow = blockRow + srow;
    const uint32_t soff = (uint32_t)(srow * PADK + skh) * 2;

    const uint32_t aLaneOff =
        (uint32_t)((wm * 64 + (lane & 15)) * PADK + (lane >> 4) * 8) * 2;
    const uint32_t bLaneOff =
        (uint32_t)((wn * 32 + (lane & 7) + (lane >> 4) * 8) * PADK +
                   ((lane >> 3) & 1) * 8) * 2;

    float acc[4][4][4];
#pragma unroll
    for (int i = 0; i < 4; i++)
#pragma unroll
        for (int j = 0; j < 4; j++)
#pragma unroll
            for (int q = 0; q < 4; q++) acc[i][j][q] = 0.f;

    for (int c = 0; c < 8; c++) {
        {
            const float* xp = X + (size_t)grow * F_IN + c * 32 + skh;
            float f[16];
#pragma unroll
            for (int j = 0; j < 4; j++) {
                float4 v = (grow < N_NODES) ? *(const float4*)(xp + j * 4)
                                            : make_float4(0.f, 0.f, 0.f, 0.f);
                f[4*j] = v.x; f[4*j+1] = v.y; f[4*j+2] = v.z; f[4*j+3] = v.w;
            }
            uint32_t ph[8], pl[8];
#pragma unroll
            for (int q = 0; q < 8; q++) {
                __nv_bfloat16 h0 = __float2bfloat16_rn(f[2*q]);
                __nv_bfloat16 h1 = __float2bfloat16_rn(f[2*q+1]);
                __nv_bfloat16 l0 = __float2bfloat16_rn(f[2*q]   - __bfloat162float(h0));
                __nv_bfloat16 l1 = __float2bfloat16_rn(f[2*q+1] - __bfloat162float(h1));
                ph[q] = (uint32_t)*(unsigned short*)&h0 |
                        ((uint32_t)*(unsigned short*)&h1 << 16);
                pl[q] = (uint32_t)*(unsigned short*)&l0 |
                        ((uint32_t)*(unsigned short*)&l1 << 16);
            }
            *(uint4*)((char*)sAhi + soff)      = make_uint4(ph[0], ph[1], ph[2], ph[3]);
            *(uint4*)((char*)sAhi + soff + 16) = make_uint4(ph[4], ph[5], ph[6], ph[7]);
            *(uint4*)((char*)sAlo + soff)      = make_uint4(pl[0], pl[1], pl[2], pl[3]);
            *(uint4*)((char*)sAlo + soff + 16) = make_uint4(pl[4], pl[5], pl[6], pl[7]);
        }
        {
            const uint4* wh = (const uint4*)(g_wt_hi + srow * F_IN + c * 32 + skh);
            const uint4* wl = (const uint4*)(g_wt_lo + srow * F_IN + c * 32 + skh);
            *(uint4*)((char*)sBhi + soff)      = wh[0];
            *(uint4*)((char*)sBhi + soff + 16) = wh[1];
            *(uint4*)((char*)sBlo + soff)      = wl[0];
            *(uint4*)((char*)sBlo + soff + 16) = wl[1];
        }
        __syncthreads();

#pragma unroll
        for (int ks = 0; ks < 2; ks++) {
            const uint32_t kb = (uint32_t)(ks * 16 * 2);
            uint32_t bh[4][2], bl[4][2];
#pragma unroll
            for (int p = 0; p < 2; p++) {
                uint32_t addr = bLaneOff + (uint32_t)(p * 16 * PADK * 2) + kb;
                uint32_t r0, r1, r2, r3;
                ldmx4(r0, r1, r2, r3, bHi + addr);
                bh[2*p][0] = r0; bh[2*p][1] = r1;
                bh[2*p+1][0] = r2; bh[2*p+1][1] = r3;
                ldmx4(r0, r1, r2, r3, bLo + addr);
                bl[2*p][0] = r0; bl[2*p][1] = r1;
                bl[2*p+1][0] = r2; bl[2*p+1][1] = r3;
            }
#pragma unroll
            for (int mt = 0; mt < 4; mt++) {
                uint32_t addr = aLaneOff + (uint32_t)(mt * 16 * PADK * 2) + kb;
                uint32_t ah[4], al[4];
                ldmx4(ah[0], ah[1], ah[2], ah[3], aHi + addr);
                ldmx4(al[0], al[1], al[2], al[3], aLo + addr);
#pragma unroll
                for (int nt = 0; nt < 4; nt++) {
                    mma_bf16(acc[mt][nt], ah, bh[nt][0], bh[nt][1]); // hi*hi
                    mma_bf16(acc[mt][nt], ah, bl[nt][0], bl[nt][1]); // hi*lo
                    mma_bf16(acc[mt][nt], al, bh[nt][0], bh[nt][1]); // lo*hi
                }
            }
        }
        __syncthreads();
    }

    // ---- epilogue: fp32 acc -> fp16 h1 ----
    const int r0 = blockRow + wm * 64 + (lane >> 2);
    const int c0 = wn * 32 + 2 * (lane & 3);
#pragma unroll
    for (int mt = 0; mt < 4; mt++) {
#pragma unroll
        for (int nt = 0; nt < 4; nt++) {
            int rA = r0 + mt * 16;
            int cc = c0 + nt * 8;
            if (rA < N_NODES)
                *(__half2*)&g_h1[(size_t)rA * H1 + cc] =
                    __floats2half2_rn(acc[mt][nt][0], acc[mt][nt][1]);
            if (rA + 8 < N_NODES)
                *(__half2*)&g_h1[(size_t)(rA + 8) * H1 + cc] =
                    __floats2half2_rn(acc[mt][nt][2], acc[mt][nt][3]);
        }
    }
}

// ---------------- Aggregation layer 1 (dim 128, fp16 gather) ---------------
// warp per node; lane handles 4 features (2x half2 = 8B) -> 256B/edge row.
__global__ __launch_bounds__(256) void k_agg1(const float* __restrict__ b1) {
    int n = blockIdx.x * 8 + (threadIdx.x >> 5);
    int lane = threadIdx.x & 31;
    if (n >= N_NODES) return;
    int s0 = g_rowptr[n], s1 = g_rowptr[n + 1];
    float4 acc = *(const float4*)&b1[lane * 4];
    const uint2* h = (const uint2*)g_h1;     // 2 half2 per uint2
    int e = s0;
    for (; e + 1 < s1; e += 2) {
        int src0 = g_col[e],     src1 = g_col[e + 1];
        float w0 = g_wgt[e],     w1 = g_wgt[e + 1];
        uint2 u0 = h[(size_t)src0 * 32 + lane];
        uint2 u1 = h[(size_t)src1 * 32 + lane];
        float2 a0 = __half22float2(*(__half2*)&u0.x);
        float2 a1v = __half22float2(*(__half2*)&u0.y);
        float2 c0 = __half22float2(*(__half2*)&u1.x);
        float2 c1 = __half22float2(*(__half2*)&u1.y);
        acc.x += w0 * a0.x + w1 * c0.x;
        acc.y += w0 * a0.y + w1 * c0.y;
        acc.z += w0 * a1v.x + w1 * c1.x;
        acc.w += w0 * a1v.y + w1 * c1.y;
    }
    if (e < s1) {
        int src = g_col[e]; float w = g_wgt[e];
        uint2 u = h[(size_t)src * 32 + lane];
        float2 a0 = __half22float2(*(__half2*)&u.x);
        float2 a1v = __half22float2(*(__half2*)&u.y);
        acc.x += w * a0.x; acc.y += w * a0.y;
        acc.z += w * a1v.x; acc.w += w * a1v.y;
    }
    acc.x = LEAKY(acc.x); acc.y = LEAKY(acc.y);
    acc.z = LEAKY(acc.z); acc.w = LEAKY(acc.w);
    ((float4*)g_a1)[(size_t)n * 32 + lane] = acc;
}

// ---------------- GEMM2: h2 = a1 @ W2  (K=128, N=16) -> fp16 ---------------
__global__ __launch_bounds__(256) void k_gemm2(const float* __restrict__ W) {
    __shared__ float Xs[16][128];
    __shared__ float Ws[128 * 16];
    const int rbase = blockIdx.x * 16;
    const int tid = threadIdx.x;
#pragma unroll
    for (int t = 0; t < 2; t++) {
        int f = tid + t * 256;
        int row = f >> 5;
        int col = (f & 31) * 4;
        *(float4*)&Xs[row][col] = *(const float4*)&g_a1[(size_t)(rbase + row) * H1 + col];
    }
    for (int i = tid; i < 128 * 16; i += 256) Ws[i] = W[i];
    __syncthreads();
    int r = tid >> 4, c = tid & 15;
    float acc = 0.f;
#pragma unroll 8
    for (int k = 0; k < 128; k++) acc += Xs[r][k] * Ws[k * 16 + c];
    g_h2[(size_t)(rbase + r) * H2 + c] = __float2half_rn(acc);
}

// ---------------- Aggregation layer 2 (dim 16, fp16): 8 thr/node -----------
__global__ __launch_bounds__(256) void k_agg2(const float* __restrict__ b2) {
    int n = blockIdx.x * 32 + (threadIdx.x >> 3);
    int f2 = threadIdx.x & 7;                 // half2 index 0..7
    if (n >= N_NODES) return;
    int s0 = g_rowptr[n], s1 = g_rowptr[n + 1];
    float accx = b2[f2 * 2], accy = b2[f2 * 2 + 1];
    const __half2* h = (const __half2*)g_h2;
    for (int e = s0; e < s1; e++) {
        float w = g_wgt[e];
        float2 v = __half22float2(h[(size_t)g_col[e] * 8 + f2]);
        accx += w * v.x; accy += w * v.y;
    }
    accx = LEAKY(accx); accy = LEAKY(accy);
    ((__half2*)g_a2)[(size_t)n * 8 + f2] = __floats2half2_rn(accx, accy);
}

// ---------------- Aggregation layer 3 (dim 16, fp16 gather) ----------------
__global__ __launch_bounds__(256) void k_agg3g() {
    int n = blockIdx.x * 32 + (threadIdx.x >> 3);
    int f2 = threadIdx.x & 7;
    if (n >= N_NODES) return;
    int s0 = g_rowptr[n], s1 = g_rowptr[n + 1];
    float accx = 0.f, accy = 0.f;
    const __half2* h = (const __half2*)g_a2;
    for (int e = s0; e < s1; e++) {
        float w = g_wgt[e];
        float2 v = __half22float2(h[(size_t)g_col[e] * 8 + f2]);
        accx += w * v.x; accy += w * v.y;
    }
    g_g3[(size_t)n * H2 + f2 * 2]     = accx;
    g_g3[(size_t)n * H2 + f2 * 2 + 1] = accy;
}

// ---------------- GEMM3: out = g3 @ W3 + b3  (K=16, N=40) ------------------
__global__ __launch_bounds__(256) void k_gemm3(const float* __restrict__ W,
                                               const float* __restrict__ b3,
                                               float* __restrict__ out) {
    __shared__ float Ws[16 * 40];
    __shared__ float Bs[40];
    __shared__ float Xs[64][17];
    const int rbase = blockIdx.x * 64;
    const int tid = threadIdx.x;
    for (int i = tid; i < 16 * 40; i += 256) Ws[i] = W[i];
    if (tid < 40) Bs[tid] = b3[tid];
#pragma unroll
    for (int t = 0; t < 4; t++) {
        int f = tid + t * 256;
        int row = f >> 4;
        int col = f & 15;
        Xs[row][col] = (rbase + row < N_NODES)
                       ? g_g3[(size_t)(rbase + row) * H2 + col] : 0.f;
    }
    __syncthreads();
#pragma unroll
    for (int t = 0; t < 10; t++) {
        int o = tid + t * 256;
        int r = o / C_OUT;
        int c = o % C_OUT;
        float acc = Bs[c];
#pragma unroll
        for (int k = 0; k < 16; k++) acc += Xs[r][k] * Ws[k * C_OUT + c];
        if (rbase + r < N_NODES)
            out[(size_t)(rbase + r) * C_OUT + c] = acc;
    }
}

// ---------------- launch ----------------------------------------------------
extern "C" void kernel_launch(void* const* d_in, const int* in_sizes, int n_in,
                              void* d_out, int out_size) {
    const float* x  = (const float*)d_in[0];
    const int*   ei = (const int*)d_in[1];     // int32 (JAX x64 disabled)
    const float* W1 = (const float*)d_in[2];
    const float* b1 = (const float*)d_in[3];
    const float* W2 = (const float*)d_in[4];
    const float* b2 = (const float*)d_in[5];
    const float* W3 = (const float*)d_in[6];
    const float* b3 = (const float*)d_in[7];
    float* out = (float*)d_out;

    const int TB = 256;
    const int gN = NBLK_N;                       // 391
    const int gE = (E_EDGES + TB - 1) / TB;      // 12500

    // CSR build
    k_init_deg<<<gN, TB>>>();
    k_hist<<<gE, TB>>>(ei);
    k_scan_block<<<gN, TB>>>();
    k_scan_sums<<<1, 512>>>(gN);
    k_scan_fixup<<<gN, TB>>>();
    k_fill_edge<<<gE, TB>>>(ei);

    // layer 1 (tensor GEMM + fp16 gather-agg)
    k_prepw<<<(F_IN * H1 + TB - 1) / TB, TB>>>(W1);
    k_gemm1<<<(N_NODES + 127) / 128, 256>>>(x);
    k_agg1<<<N_NODES / 8, 256>>>(b1);
    // layer 2
    k_gemm2<<<N_NODES / 16, 256>>>(W2);
    k_agg2<<<(N_NODES + 31) / 32, 256>>>(b2);
    // layer 3 (agg first, then GEMM with bias)
    k_agg3g<<<(N_NODES + 31) / 32, 256>>>();
    k_gemm3<<<(N_NODES + 63) / 64, 256>>>(W3, b3, out);
}

// round 6
// speedup vs baseline: 1.4128x; 1.0605x over previous
#include <cuda_runtime.h>
#include <cuda_bf16.h>
#include <cuda_fp16.h>
#include <math.h>
#include <stdint.h>

#define N_NODES 100000
#define F_IN    256
#define H1      128
#define H2      16
#define C_OUT   40
#define E_EDGES 3200000
#define E_TOT   (E_EDGES + N_NODES)
#define NBLK_N  ((N_NODES + 255) / 256)   // 391

// ---------------- scratch (static device arrays; no runtime alloc) ---------
__device__ __align__(16) __half g_h1[N_NODES * H1];     // x @ W1 (fp16)
__device__ __align__(16) __half g_a1[N_NODES * H1];     // leaky(agg(h1)+b1) fp16
__device__ __align__(16) __half g_h2[N_NODES * H2];     // a1 @ W2 (fp16)
__device__ __align__(16) __half g_a2[N_NODES * H2];     // leaky(agg(h2)+b2) fp16
__device__ __align__(16) float  g_g3[N_NODES * H2];     // agg(a2) fp32
__device__ __align__(16) __nv_bfloat16 g_wt_hi[H1 * F_IN];  // W1^T hi split [n][k]
__device__ __align__(16) __nv_bfloat16 g_wt_lo[H1 * F_IN];  // W1^T lo split [n][k]
__device__ int   g_deg[N_NODES];
__device__ float g_dis[N_NODES];          // deg^{-1/2}
__device__ int   g_rowptr[N_NODES + 1];
__device__ int   g_cursor[N_NODES];
__device__ __align__(8) int2 g_edge[E_TOT];   // (src, wgt-bits) per CSR slot
__device__ int   g_bsums[512];
__device__ int   g_boff[512];

#define LEAKY(v) ((v) > 0.f ? (v) : 0.2f * (v))

// ===================== portable tensor-core helpers (sm_80+) ================
__device__ __forceinline__ uint32_t smem_u32(const void* p) {
    uint32_t a;
    asm("{ .reg .u64 t; cvta.to.shared.u64 t, %1; cvt.u32.u64 %0, t; }"
        : "=r"(a) : "l"(p));
    return a;
}
__device__ __forceinline__ void ldmx4(uint32_t& r0, uint32_t& r1,
                                      uint32_t& r2, uint32_t& r3, uint32_t a) {
    asm volatile("ldmatrix.sync.aligned.m8n8.x4.shared.b16 {%0,%1,%2,%3}, [%4];"
                 : "=r"(r0), "=r"(r1), "=r"(r2), "=r"(r3) : "r"(a));
}
__device__ __forceinline__ void mma_bf16(float* d, const uint32_t* a,
                                         uint32_t b0, uint32_t b1) {
    asm volatile(
        "mma.sync.aligned.m16n8k16.row.col.f32.bf16.bf16.f32 "
        "{%0,%1,%2,%3}, {%4,%5,%6,%7}, {%8,%9}, {%0,%1,%2,%3};"
        : "+f"(d[0]), "+f"(d[1]), "+f"(d[2]), "+f"(d[3])
        : "r"(a[0]), "r"(a[1]), "r"(a[2]), "r"(a[3]), "r"(b0), "r"(b1));
}

// ---------------- CSR construction ----------------------------------------
__global__ void k_init_deg() {
    int i = blockIdx.x * blockDim.x + threadIdx.x;
    if (i < N_NODES) g_deg[i] = 1;   // self loop
}
__global__ void k_hist(const int* __restrict__ ei) {
    int e = blockIdx.x * blockDim.x + threadIdx.x;
    if (e < E_EDGES) atomicAdd(&g_deg[ei[E_EDGES + e]], 1);
}
__global__ void k_scan_block() {
    __shared__ int s[256];
    int b = blockIdx.x, t = threadIdx.x;
    int i = b * 256 + t;
    int v = (i < N_NODES) ? g_deg[i] : 0;
    if (i < N_NODES) g_dis[i] = rsqrtf((float)v);
    s[t] = v;
    __syncthreads();
#pragma unroll
    for (int off = 1; off < 256; off <<= 1) {
        int add = (t >= off) ? s[t - off] : 0;
        __syncthreads();
        s[t] += add;
        __syncthreads();
    }
    int incl = s[t];
    if (i < N_NODES) g_rowptr[i] = incl - v;
    if (t == 255) g_bsums[b] = incl;
}
__global__ void k_scan_sums(int nblk) {
    __shared__ int s[512];
    int t = threadIdx.x;
    int v = (t < nblk) ? g_bsums[t] : 0;
    s[t] = v;
    __syncthreads();
#pragma unroll
    for (int off = 1; off < 512; off <<= 1) {
        int add = (t >= off) ? s[t - off] : 0;
        __syncthreads();
        s[t] += add;
        __syncthreads();
    }
    int incl = s[t];
    if (t < nblk) g_boff[t] = incl - v;
    if (t == 511) g_rowptr[N_NODES] = incl;
}
__global__ void k_scan_fixup() {   // + self-loop fill + cursor init
    int i = blockIdx.x * blockDim.x + threadIdx.x;
    if (i < N_NODES) {
        int v = g_rowptr[i] + g_boff[i >> 8];
        g_rowptr[i] = v;
        g_cursor[i] = v + 1;
        float d = g_dis[i];
        g_edge[v] = make_int2(i, __float_as_int(d * d));
    }
}
__global__ void k_fill_edge(const int* __restrict__ ei) {
    int e = blockIdx.x * blockDim.x + threadIdx.x;
    if (e < E_EDGES) {
        int s = ei[e];
        int d = ei[E_EDGES + e];
        int p = atomicAdd(&g_cursor[d], 1);
        float w = g_dis[s] * g_dis[d];
        g_edge[p] = make_int2(s, __float_as_int(w));
    }
}

// ---------------- W1 transpose + bf16 split --------------------------------
__global__ void k_prepw(const float* __restrict__ W1) {
    int idx = blockIdx.x * blockDim.x + threadIdx.x;  // 32768
    if (idx < F_IN * H1) {
        int k = idx >> 7, n = idx & 127;
        float w = W1[idx];
        __nv_bfloat16 hi = __float2bfloat16_rn(w);
        float lo = w - __bfloat162float(hi);
        g_wt_hi[n * F_IN + k] = hi;
        g_wt_lo[n * F_IN + k] = __float2bfloat16_rn(lo);
    }
}

// ---------------- GEMM1: h1 = X @ W1, bf16 split via mma.sync --------------
// CTA 128x128, BK=32, 8 warps in 2(m) x 4(n). Register-prefetch pipeline.
#define PADK 40
__global__ __launch_bounds__(256) void k_gemm1(const float* __restrict__ X) {
    __shared__ __align__(16) __nv_bfloat16 sAhi[128 * PADK];
    __shared__ __align__(16) __nv_bfloat16 sAlo[128 * PADK];
    __shared__ __align__(16) __nv_bfloat16 sBhi[128 * PADK];
    __shared__ __align__(16) __nv_bfloat16 sBlo[128 * PADK];

    const int tid = threadIdx.x, wid = tid >> 5, lane = tid & 31;
    const int wm = wid & 1, wn = wid >> 1;          // warp grid 2x4
    const int blockRow = blockIdx.x * 128;

    const uint32_t aHi = smem_u32(sAhi), aLo = smem_u32(sAlo);
    const uint32_t bHi = smem_u32(sBhi), bLo = smem_u32(sBlo);

    const int srow = tid >> 1;          // 0..127
    const int skh  = (tid & 1) * 16;    // 0 or 16
    const int grow = blockRow + srow;
    const bool rowOK = (grow < N_NODES);
    const uint32_t soff = (uint32_t)(srow * PADK + skh) * 2;

    const uint32_t aLaneOff =
        (uint32_t)((wm * 64 + (lane & 15)) * PADK + (lane >> 4) * 8) * 2;
    const uint32_t bLaneOff =
        (uint32_t)((wn * 32 + (lane & 7) + (lane >> 4) * 8) * PADK +
                   ((lane >> 3) & 1) * 8) * 2;

    float acc[4][4][4];
#pragma unroll
    for (int i = 0; i < 4; i++)
#pragma unroll
        for (int j = 0; j < 4; j++)
#pragma unroll
            for (int q = 0; q < 4; q++) acc[i][j][q] = 0.f;

    // prefetch registers
    float f[16];
    uint4 whv[2], wlv[2];

    // load chunk 0
    {
        const float* xp = X + (size_t)grow * F_IN + skh;
#pragma unroll
        for (int j = 0; j < 4; j++) {
            float4 v = rowOK ? *(const float4*)(xp + j * 4)
                             : make_float4(0.f, 0.f, 0.f, 0.f);
            f[4*j] = v.x; f[4*j+1] = v.y; f[4*j+2] = v.z; f[4*j+3] = v.w;
        }
        const uint4* wh = (const uint4*)(g_wt_hi + srow * F_IN + skh);
        const uint4* wl = (const uint4*)(g_wt_lo + srow * F_IN + skh);
        whv[0] = wh[0]; whv[1] = wh[1];
        wlv[0] = wl[0]; wlv[1] = wl[1];
    }

    for (int c = 0; c < 8; c++) {
        // ---- convert prefetched regs -> smem ----
        {
            uint32_t ph[8], pl[8];
#pragma unroll
            for (int q = 0; q < 8; q++) {
                __nv_bfloat16 h0 = __float2bfloat16_rn(f[2*q]);
                __nv_bfloat16 h1 = __float2bfloat16_rn(f[2*q+1]);
                __nv_bfloat16 l0 = __float2bfloat16_rn(f[2*q]   - __bfloat162float(h0));
                __nv_bfloat16 l1 = __float2bfloat16_rn(f[2*q+1] - __bfloat162float(h1));
                ph[q] = (uint32_t)*(unsigned short*)&h0 |
                        ((uint32_t)*(unsigned short*)&h1 << 16);
                pl[q] = (uint32_t)*(unsigned short*)&l0 |
                        ((uint32_t)*(unsigned short*)&l1 << 16);
            }
            *(uint4*)((char*)sAhi + soff)      = make_uint4(ph[0], ph[1], ph[2], ph[3]);
            *(uint4*)((char*)sAhi + soff + 16) = make_uint4(ph[4], ph[5], ph[6], ph[7]);
            *(uint4*)((char*)sAlo + soff)      = make_uint4(pl[0], pl[1], pl[2], pl[3]);
            *(uint4*)((char*)sAlo + soff + 16) = make_uint4(pl[4], pl[5], pl[6], pl[7]);
            *(uint4*)((char*)sBhi + soff)      = whv[0];
            *(uint4*)((char*)sBhi + soff + 16) = whv[1];
            *(uint4*)((char*)sBlo + soff)      = wlv[0];
            *(uint4*)((char*)sBlo + soff + 16) = wlv[1];
        }
        __syncthreads();

        // ---- issue next chunk's global loads (hidden behind MMAs) ----
        if (c < 7) {
            const float* xp = X + (size_t)grow * F_IN + (c + 1) * 32 + skh;
#pragma unroll
            for (int j = 0; j < 4; j++) {
                float4 v = rowOK ? *(const float4*)(xp + j * 4)
                                 : make_float4(0.f, 0.f, 0.f, 0.f);
                f[4*j] = v.x; f[4*j+1] = v.y; f[4*j+2] = v.z; f[4*j+3] = v.w;
            }
            const uint4* wh = (const uint4*)(g_wt_hi + srow * F_IN + (c + 1) * 32 + skh);
            const uint4* wl = (const uint4*)(g_wt_lo + srow * F_IN + (c + 1) * 32 + skh);
            whv[0] = wh[0]; whv[1] = wh[1];
            wlv[0] = wl[0]; wlv[1] = wl[1];
        }

#pragma unroll
        for (int ks = 0; ks < 2; ks++) {
            const uint32_t kb = (uint32_t)(ks * 16 * 2);
            uint32_t bh[4][2], bl[4][2];
#pragma unroll
            for (int p = 0; p < 2; p++) {
                uint32_t addr = bLaneOff + (uint32_t)(p * 16 * PADK * 2) + kb;
                uint32_t r0, r1, r2, r3;
                ldmx4(r0, r1, r2, r3, bHi + addr);
                bh[2*p][0] = r0; bh[2*p][1] = r1;
                bh[2*p+1][0] = r2; bh[2*p+1][1] = r3;
                ldmx4(r0, r1, r2, r3, bLo + addr);
                bl[2*p][0] = r0; bl[2*p][1] = r1;
                bl[2*p+1][0] = r2; bl[2*p+1][1] = r3;
            }
#pragma unroll
            for (int mt = 0; mt < 4; mt++) {
                uint32_t addr = aLaneOff + (uint32_t)(mt * 16 * PADK * 2) + kb;
                uint32_t ah[4], al[4];
                ldmx4(ah[0], ah[1], ah[2], ah[3], aHi + addr);
                ldmx4(al[0], al[1], al[2], al[3], aLo + addr);
#pragma unroll
                for (int nt = 0; nt < 4; nt++) {
                    mma_bf16(acc[mt][nt], ah, bh[nt][0], bh[nt][1]); // hi*hi
                    mma_bf16(acc[mt][nt], ah, bl[nt][0], bl[nt][1]); // hi*lo
                    mma_bf16(acc[mt][nt], al, bh[nt][0], bh[nt][1]); // lo*hi
                }
            }
        }
        __syncthreads();
    }

    // ---- epilogue: fp32 acc -> fp16 h1 ----
    const int r0 = blockRow + wm * 64 + (lane >> 2);
    const int c0 = wn * 32 + 2 * (lane & 3);
#pragma unroll
    for (int mt = 0; mt < 4; mt++) {
#pragma unroll
        for (int nt = 0; nt < 4; nt++) {
            int rA = r0 + mt * 16;
            int cc = c0 + nt * 8;
            if (rA < N_NODES)
                *(__half2*)&g_h1[(size_t)rA * H1 + cc] =
                    __floats2half2_rn(acc[mt][nt][0], acc[mt][nt][1]);
            if (rA + 8 < N_NODES)
                *(__half2*)&g_h1[(size_t)(rA + 8) * H1 + cc] =
                    __floats2half2_rn(acc[mt][nt][2], acc[mt][nt][3]);
        }
    }
}

// ---------------- Aggregation layer 1 (dim 128, fp16 gather) ---------------
// warp per node; lane handles 4 features (uint2 = 2x half2), unroll 4.
__global__ __launch_bounds__(256) void k_agg1(const float* __restrict__ b1) {
    int n = blockIdx.x * 8 + (threadIdx.x >> 5);
    int lane = threadIdx.x & 31;
    if (n >= N_NODES) return;
    int s0 = g_rowptr[n], s1 = g_rowptr[n + 1];
    float4 acc = *(const float4*)&b1[lane * 4];
    const uint2* h = (const uint2*)g_h1;
    int e = s0;
    for (; e + 3 < s1; e += 4) {
        int2 E0 = g_edge[e],     E1 = g_edge[e + 1];
        int2 E2 = g_edge[e + 2], E3 = g_edge[e + 3];
        uint2 u0 = h[(size_t)E0.x * 32 + lane];
        uint2 u1 = h[(size_t)E1.x * 32 + lane];
        uint2 u2 = h[(size_t)E2.x * 32 + lane];
        uint2 u3 = h[(size_t)E3.x * 32 + lane];
        float w0 = __int_as_float(E0.y), w1 = __int_as_float(E1.y);
        float w2 = __int_as_float(E2.y), w3 = __int_as_float(E3.y);
        float2 p0 = __half22float2(*(__half2*)&u0.x), q0 = __half22float2(*(__half2*)&u0.y);
        float2 p1 = __half22float2(*(__half2*)&u1.x), q1 = __half22float2(*(__half2*)&u1.y);
        float2 p2 = __half22float2(*(__half2*)&u2.x), q2 = __half22float2(*(__half2*)&u2.y);
        float2 p3 = __half22float2(*(__half2*)&u3.x), q3 = __half22float2(*(__half2*)&u3.y);
        acc.x += w0 * p0.x + w1 * p1.x + w2 * p2.x + w3 * p3.x;
        acc.y += w0 * p0.y + w1 * p1.y + w2 * p2.y + w3 * p3.y;
        acc.z += w0 * q0.x + w1 * q1.x + w2 * q2.x + w3 * q3.x;
        acc.w += w0 * q0.y + w1 * q1.y + w2 * q2.y + w3 * q3.y;
    }
    for (; e < s1; e++) {
        int2 E = g_edge[e];
        float w = __int_as_float(E.y);
        uint2 u = h[(size_t)E.x * 32 + lane];
        float2 p = __half22float2(*(__half2*)&u.x);
        float2 q = __half22float2(*(__half2*)&u.y);
        acc.x += w * p.x; acc.y += w * p.y;
        acc.z += w * q.x; acc.w += w * q.y;
    }
    acc.x = LEAKY(acc.x); acc.y = LEAKY(acc.y);
    acc.z = LEAKY(acc.z); acc.w = LEAKY(acc.w);
    __half2 o0 = __floats2half2_rn(acc.x, acc.y);
    __half2 o1 = __floats2half2_rn(acc.z, acc.w);
    uint2 ov = make_uint2(*(uint32_t*)&o0, *(uint32_t*)&o1);
    ((uint2*)g_a1)[(size_t)n * 32 + lane] = ov;
}

// ---------------- GEMM2: h2 = a1 @ W2  (K=128, N=16) -> fp16 ---------------
__global__ __launch_bounds__(256) void k_gemm2(const float* __restrict__ W) {
    __shared__ float Xs[16][128];
    __shared__ float Ws[128 * 16];
    const int rbase = blockIdx.x * 16;
    const int tid = threadIdx.x;
    // load 16 rows x 128 cols of fp16 a1 (each thread: 8 halves = uint4)
    {
        int row = tid >> 4;
        int cg  = (tid & 15) * 8;
        uint4 u = *(const uint4*)&g_a1[(size_t)(rbase + row) * H1 + cg];
        const __half2* hp = (const __half2*)&u;
#pragma unroll
        for (int j = 0; j < 4; j++) {
            float2 v = __half22float2(hp[j]);
            Xs[row][cg + 2*j]     = v.x;
            Xs[row][cg + 2*j + 1] = v.y;
        }
    }
    for (int i = tid; i < 128 * 16; i += 256) Ws[i] = W[i];
    __syncthreads();
    int r = tid >> 4, c = tid & 15;
    float acc = 0.f;
#pragma unroll 8
    for (int k = 0; k < 128; k++) acc += Xs[r][k] * Ws[k * 16 + c];
    g_h2[(size_t)(rbase + r) * H2 + c] = __float2half_rn(acc);
}

// ---------------- Aggregation layer 2 (dim 16, fp16): 8 thr/node -----------
__global__ __launch_bounds__(256) void k_agg2(const float* __restrict__ b2) {
    int n = blockIdx.x * 32 + (threadIdx.x >> 3);
    int f2 = threadIdx.x & 7;                 // half2 index 0..7
    if (n >= N_NODES) return;
    int s0 = g_rowptr[n], s1 = g_rowptr[n + 1];
    float accx = b2[f2 * 2], accy = b2[f2 * 2 + 1];
    const __half2* h = (const __half2*)g_h2;
    int e = s0;
    for (; e + 1 < s1; e += 2) {
        int2 E0 = g_edge[e], E1 = g_edge[e + 1];
        float w0 = __int_as_float(E0.y), w1 = __int_as_float(E1.y);
        float2 v0 = __half22float2(h[(size_t)E0.x * 8 + f2]);
        float2 v1 = __half22float2(h[(size_t)E1.x * 8 + f2]);
        accx += w0 * v0.x + w1 * v1.x;
        accy += w0 * v0.y + w1 * v1.y;
    }
    if (e < s1) {
        int2 E = g_edge[e];
        float w = __int_as_float(E.y);
        float2 v = __half22float2(h[(size_t)E.x * 8 + f2]);
        accx += w * v.x; accy += w * v.y;
    }
    accx = LEAKY(accx); accy = LEAKY(accy);
    ((__half2*)g_a2)[(size_t)n * 8 + f2] = __floats2half2_rn(accx, accy);
}

// ---------------- Aggregation layer 3 (dim 16, fp16 gather) ----------------
__global__ __launch_bounds__(256) void k_agg3g() {
    int n = blockIdx.x * 32 + (threadIdx.x >> 3);
    int f2 = threadIdx.x & 7;
    if (n >= N_NODES) return;
    int s0 = g_rowptr[n], s1 = g_rowptr[n + 1];
    float accx = 0.f, accy = 0.f;
    const __half2* h = (const __half2*)g_a2;
    int e = s0;
    for (; e + 1 < s1; e += 2) {
        int2 E0 = g_edge[e], E1 = g_edge[e + 1];
        float w0 = __int_as_float(E0.y), w1 = __int_as_float(E1.y);
        float2 v0 = __half22float2(h[(size_t)E0.x * 8 + f2]);
        float2 v1 = __half22float2(h[(size_t)E1.x * 8 + f2]);
        accx += w0 * v0.x + w1 * v1.x;
        accy += w0 * v0.y + w1 * v1.y;
    }
    if (e < s1) {
        int2 E = g_edge[e];
        float w = __int_as_float(E.y);
        float2 v = __half22float2(h[(size_t)E.x * 8 + f2]);
        accx += w * v.x; accy += w * v.y;
    }
    g_g3[(size_t)n * H2 + f2 * 2]     = accx;
    g_g3[(size_t)n * H2 + f2 * 2 + 1] = accy;
}

// ---------------- GEMM3: out = g3 @ W3 + b3  (K=16, N=40) ------------------
__global__ __launch_bounds__(256) void k_gemm3(const float* __restrict__ W,
                                               const float* __restrict__ b3,
                                               float* __restrict__ out) {
    __shared__ float Ws[16 * 40];
    __shared__ float Bs[40];
    __shared__ float Xs[64][17];
    const int rbase = blockIdx.x * 64;
    const int tid = threadIdx.x;
    for (int i = tid; i < 16 * 40; i += 256) Ws[i] = W[i];
    if (tid < 40) Bs[tid] = b3[tid];
#pragma unroll
    for (int t = 0; t < 4; t++) {
        int f = tid + t * 256;
        int row = f >> 4;
        int col = f & 15;
        Xs[row][col] = (rbase + row < N_NODES)
                       ? g_g3[(size_t)(rbase + row) * H2 + col] : 0.f;
    }
    __syncthreads();
#pragma unroll
    for (int t = 0; t < 10; t++) {
        int o = tid + t * 256;
        int r = o / C_OUT;
        int c = o % C_OUT;
        float acc = Bs[c];
#pragma unroll
        for (int k = 0; k < 16; k++) acc += Xs[r][k] * Ws[k * C_OUT + c];
        if (rbase + r < N_NODES)
            out[(size_t)(rbase + r) * C_OUT + c] = acc;
    }
}

// ---------------- launch ----------------------------------------------------
extern "C" void kernel_launch(void* const* d_in, const int* in_sizes, int n_in,
                              void* d_out, int out_size) {
    const float* x  = (const float*)d_in[0];
    const int*   ei = (const int*)d_in[1];     // int32 (JAX x64 disabled)
    const float* W1 = (const float*)d_in[2];
    const float* b1 = (const float*)d_in[3];
    const float* W2 = (const float*)d_in[4];
    const float* b2 = (const float*)d_in[5];
    const float* W3 = (const float*)d_in[6];
    const float* b3 = (const float*)d_in[7];
    float* out = (float*)d_out;

    const int TB = 256;
    const int gN = NBLK_N;                       // 391
    const int gE = (E_EDGES + TB - 1) / TB;      // 12500

    // CSR build
    k_init_deg<<<gN, TB>>>();
    k_hist<<<gE, TB>>>(ei);
    k_scan_block<<<gN, TB>>>();
    k_scan_sums<<<1, 512>>>(gN);
    k_scan_fixup<<<gN, TB>>>();
    k_fill_edge<<<gE, TB>>>(ei);

    // layer 1 (tensor GEMM + fp16 gather-agg)
    k_prepw<<<(F_IN * H1 + TB - 1) / TB, TB>>>(W1);
    k_gemm1<<<(N_NODES + 127) / 128, 256>>>(x);
    k_agg1<<<N_NODES / 8, 256>>>(b1);
    // layer 2
    k_gemm2<<<N_NODES / 16, 256>>>(W2);
    k_agg2<<<(N_NODES + 31) / 32, 256>>>(b2);
    // layer 3 (agg first, then GEMM with bias)
    k_agg3g<<<(N_NODES + 31) / 32, 256>>>();
    k_gemm3<<<(N_NODES + 63) / 64, 256>>>(W3, b3, out);
}